// round 8
// baseline (speedup 1.0000x reference)
#include <cuda_runtime.h>
#include <math.h>
#include <stdint.h>

#define IN_DIM 512
#define HID    1024
#define MEMD   1024
#define OUTD   512
#define BATCH  4096

#define TM 128
#define TN 128
#define KC 32
#define NTHREADS 256
#define CH_FLOATS (128 * 32)
#define CH_BYTES  (CH_FLOATS * 4)        // 16384
#define SMEM_BYTES (6 * CH_BYTES)        // 98304, 2 CTAs/SM
#define GRID 296
#define VB   40                          // vector-recurrence blocks

// ---------------- device scratch ----------------
__device__ __align__(16) float g_xT [(size_t)BATCH * IN_DIM];
__device__ __align__(16) float g_pre[3][(size_t)BATCH * HID];
__device__ __align__(16) float g_rgm[(size_t)BATCH * MEMD];
__device__ __align__(16) float g_hid[(size_t)BATCH * HID];

__device__ __align__(16) float g_wb_inp[HID * IN_DIM];
__device__ __align__(16) float g_wb_ig [HID * IN_DIM];
__device__ __align__(16) float g_wb_rg [HID * IN_DIM];
__device__ __align__(16) float g_wb_dec[MEMD * MEMD];
__device__ __align__(16) float g_wb_ho [OUTD * HID];

__device__ __align__(16) float g_out_v[OUTD];
__device__ __align__(16) float g_mem_v[MEMD];
__device__ __align__(16) float g_prod_v[HID];
__device__ __align__(16) float g_rgmem_v[MEMD];
__device__ __align__(16) float g_wg_v[MEMD];
__device__ __align__(16) float g_hid_v[HID];
__device__ __align__(16) float g_c_inp[HID];
__device__ __align__(16) float g_c_ig[HID];
__device__ __align__(16) float g_c_rg[MEMD];

// barriers (cnt returns to 0 each use; gen monotonic across replays)
__device__ unsigned g_cntA = 0, g_genA = 0;
__device__ unsigned g_cntB = 0, g_genB = 0;
// dynamic tile counters (reset at start of each replay by block 0)
__device__ unsigned g_t1 = 0, g_t2 = 0, g_t3 = 0;

struct P {
    const float *input;
    const float *W_ig, *b_ig, *W_rig, *b_rig, *W_mig, *b_mig;
    const float *W_inp, *b_inp, *W_rinp, *b_rinp;
    const float *W_rg, *b_rg, *W_rrg, *b_rrg, *W_mrg, *b_mrg;
    const float *W_dec, *b_dec;
    const float *W_wg, *b_wg, *W_rwg, *b_rwg, *W_mwg, *b_mwg;
    const float *W_enc, *b_enc, *w_ho;
};

__device__ __forceinline__ float sigf(float x) { return 1.0f / (1.0f + expf(-x)); }
__device__ __forceinline__ float warp_sum(float v) {
    #pragma unroll
    for (int o = 16; o; o >>= 1) v += __shfl_xor_sync(0xFFFFFFFFu, v, o);
    return v;
}
__device__ __forceinline__ float dot4(float4 a, float4 b) {
    return a.x * b.x + a.y * b.y + a.z * b.z + a.w * b.w;
}
__device__ __forceinline__ uint32_t f2tf32(float f) {
    uint32_t r;
    asm("cvt.rna.tf32.f32 %0, %1;" : "=r"(r) : "f"(f));
    return r;
}
__device__ __forceinline__ float rnd_tf32(float f) { return __uint_as_float(f2tf32(f)); }

__device__ __forceinline__ void mma1688(float* c, const uint32_t* a, const uint32_t* b) {
    asm volatile(
        "mma.sync.aligned.m16n8k8.row.col.f32.tf32.tf32.f32 "
        "{%0,%1,%2,%3}, {%4,%5,%6,%7}, {%8,%9}, {%0,%1,%2,%3};"
        : "+f"(c[0]), "+f"(c[1]), "+f"(c[2]), "+f"(c[3])
        : "r"(a[0]), "r"(a[1]), "r"(a[2]), "r"(a[3]), "r"(b[0]), "r"(b[1]));
}
__device__ __forceinline__ void cp16(uint32_t dst, const void* src) {
    asm volatile("cp.async.cg.shared.global [%0], [%1], 16;" :: "r"(dst), "l"(src));
}
#define CP_COMMIT() asm volatile("cp.async.commit_group;" ::: "memory")
#define CP_WAIT(n)  asm volatile("cp.async.wait_group %0;" :: "n"(n) : "memory")
__device__ __forceinline__ uint32_t smem_u32(const void* p) {
    uint32_t a;
    asm("{ .reg .u64 t; cvta.to.shared.u64 t, %1; cvt.u32.u64 %0, t; }" : "=r"(a) : "l"(p));
    return a;
}

// ---------------- grid barrier over `target` co-resident blocks ----------------
__device__ __forceinline__ void gbar(unsigned* cnt, unsigned* gen, unsigned target, unsigned* my) {
    __syncthreads();
    if (threadIdx.x == 0) {
        __threadfence();
        unsigned a = atomicAdd(cnt, 1);
        if (a == target - 1) {
            *cnt = 0;
            __threadfence();
            atomicAdd(gen, 1);
        } else {
            while (*(volatile unsigned*)gen == *my) __nanosleep(64);
        }
        __threadfence();
    }
    __syncthreads();
    (*my)++;
}

// ---------------- GEMM tile: C[128,128] tile of A[M,K] @ B[N,K]^T ----------------
// 3-stage cp.async, XOR-swizzled smem (16B granule q at q^(r&7)), 1 barrier/chunk.
template <int MODE, int ROUND>
__device__ __forceinline__ void gemm_tile(
    float* smem, uint32_t smb, int tid,
    const float* __restrict__ A, const float* __restrict__ B, float* __restrict__ C,
    int K, int ldC, int m0, int n0,
    const float* __restrict__ bias, const float* __restrict__ addm)
{
    const int wid = tid >> 5, lane = tid & 31;
    const int g = lane >> 2, t4 = lane & 3;
    const int wm = (wid >> 2) * 64, wn = (wid & 3) * 32;
    const int nc = K / KC;
    const int ld_q = tid & 7;
    const int ld_r0 = tid >> 3;

    float acc[4][4][4];
    #pragma unroll
    for (int i = 0; i < 4; i++)
        #pragma unroll
        for (int j = 0; j < 4; j++)
            #pragma unroll
            for (int q = 0; q < 4; q++) acc[i][j][q] = 0.f;

    auto issue = [&](int k0, int buf) {
        uint32_t ab = smb + buf * CH_BYTES;
        uint32_t bb = smb + (3 + buf) * CH_BYTES;
        #pragma unroll
        for (int j = 0; j < 4; j++) {
            int r = ld_r0 + j * 32;
            uint32_t dst = (uint32_t)((r * 8 + (ld_q ^ (r & 7))) * 16);
            cp16(ab + dst, A + (size_t)(m0 + r) * K + k0 + ld_q * 4);
            cp16(bb + dst, B + (size_t)(n0 + r) * K + k0 + ld_q * 4);
        }
        CP_COMMIT();
    };
    auto compute = [&](int buf) {
        const uint32_t* as_ = (const uint32_t*)(smem + buf * CH_FLOATS);
        const uint32_t* bs_ = (const uint32_t*)(smem + (3 + buf) * CH_FLOATS);
        #pragma unroll
        for (int ks = 0; ks < 4; ks++) {
            const int c0 = ((2 * ks) ^ g) * 4 + t4;
            const int c1 = c0 ^ 4;
            uint32_t af[4][4], bf[4][2];
            #pragma unroll
            for (int mt = 0; mt < 4; mt++) {
                int m = wm + mt * 16 + g;
                af[mt][0] = as_[m * 32 + c0];
                af[mt][1] = as_[(m + 8) * 32 + c0];
                af[mt][2] = as_[m * 32 + c1];
                af[mt][3] = as_[(m + 8) * 32 + c1];
            }
            #pragma unroll
            for (int nt = 0; nt < 4; nt++) {
                int n = wn + nt * 8 + g;
                bf[nt][0] = bs_[n * 32 + c0];
                bf[nt][1] = bs_[n * 32 + c1];
            }
            #pragma unroll
            for (int mt = 0; mt < 4; mt++)
                #pragma unroll
                for (int nt = 0; nt < 4; nt++)
                    mma1688(acc[mt][nt], af[mt], bf[nt]);
        }
    };

    issue(0, 0);
    issue(KC, 1);
    for (int c = 0; c < nc; c++) {
        CP_WAIT(1);
        __syncthreads();
        if (c + 2 < nc) issue((c + 2) * KC, (c + 2) % 3);
        compute(c % 3);
    }
    __syncthreads();

    float* stg = smem;
    #pragma unroll
    for (int mt = 0; mt < 4; mt++) {
        #pragma unroll
        for (int nt = 0; nt < 4; nt++) {
            int rr = wm + mt * 16 + g;
            int cc = wn + nt * 8 + t4 * 2;
            *(float2*)(stg + rr * 132 + cc)       = make_float2(acc[mt][nt][0], acc[mt][nt][1]);
            *(float2*)(stg + (rr + 8) * 132 + cc) = make_float2(acc[mt][nt][2], acc[mt][nt][3]);
        }
    }
    __syncthreads();
    #pragma unroll
    for (int j = 0; j < 16; j++) {
        int s = j * NTHREADS + tid;
        int r = s >> 5, cq = s & 31;
        int m = m0 + r, n = n0 + cq * 4;
        float4 v = *(float4*)(stg + r * 132 + cq * 4);
        if (MODE == 1) {
            const float4 bv = *(const float4*)(bias + n);
            const float4 av = *(const float4*)(addm + (size_t)m * ldC + n);
            v.x += bv.x + av.x; v.y += bv.y + av.y;
            v.z += bv.z + av.z; v.w += bv.w + av.w;
        }
        if (ROUND) {
            v.x = rnd_tf32(v.x); v.y = rnd_tf32(v.y);
            v.z = rnd_tf32(v.z); v.w = rnd_tf32(v.w);
        }
        *(float4*)(C + (size_t)m * ldC + n) = v;
    }
    __syncthreads();
}

// ---------------- the mega-kernel ----------------
__global__ __launch_bounds__(NTHREADS, 2) void k_main(P p, float* __restrict__ dout) {
    extern __shared__ float smem[];
    __shared__ unsigned s_tk;
    const uint32_t smb = smem_u32(smem);
    const int tid = threadIdx.x, wid = tid >> 5, lane = tid & 31;
    const int bid = blockIdx.x;
    unsigned myA = *(volatile unsigned*)&g_genA;
    unsigned myB = *(volatile unsigned*)&g_genB;

    if (bid == 0 && tid == 0) { g_t1 = 0; g_t2 = 0; g_t3 = 0; }

    // ======== phase 0 (all blocks): weight prep + transpose + step-0 state ========
    {
        const int HALF = HID * IN_DIM / 4;
        const int FULL = MEMD * MEMD / 4;
        int total = 3 * HALF + FULL + HALF;
        for (int i = bid * NTHREADS + tid; i < total; i += GRID * NTHREADS) {
            const float4* src; float4* dst; int j = i;
            if (j < HALF)                { src = (const float4*)p.W_inp; dst = (float4*)g_wb_inp; }
            else if ((j -= HALF) < HALF) { src = (const float4*)p.W_ig;  dst = (float4*)g_wb_ig; }
            else if ((j -= HALF) < HALF) { src = (const float4*)p.W_rg;  dst = (float4*)g_wb_rg; }
            else if ((j -= HALF) < FULL) { src = (const float4*)p.W_dec; dst = (float4*)g_wb_dec; }
            else { j -= FULL;              src = (const float4*)p.w_ho;  dst = (float4*)g_wb_ho; }
            float4 v = src[j];
            v.x = rnd_tf32(v.x); v.y = rnd_tf32(v.y); v.z = rnd_tf32(v.z); v.w = rnd_tf32(v.w);
            dst[j] = v;
        }
    }
    {
        float (*tile)[33] = (float(*)[33])smem;
        const int tx = tid & 31, ty8 = tid >> 5;
        for (int t = bid; t < 2048; t += GRID) {
            int bx = (t & 127) * 32;
            int by = (t >> 7) * 32;
            #pragma unroll
            for (int j = ty8; j < 32; j += 8)
                tile[j][tx] = p.input[(size_t)(by + j) * BATCH + bx + tx];
            __syncthreads();
            #pragma unroll
            for (int j = ty8; j < 32; j += 8)
                g_xT[(size_t)(bx + j) * IN_DIM + by + tx] = rnd_tf32(tile[tx][j]);
            __syncthreads();
        }
    }
    for (int h = bid * NTHREADS + tid; h < HID; h += GRID * NTHREADS) {
        float pbi = p.b_inp[h] + p.b_rinp[h];
        float pig = p.b_ig[h] + p.b_mig[h] + p.b_rig[h];
        float pwg = p.b_wg[h] + p.b_mwg[h] + p.b_rwg[h];
        __stcg(&g_hid_v[h], p.b_dec[h] + sigf(pbi) * sigf(pig));
        __stcg(&g_wg_v[h], sigf(pwg));
    }
    gbar(&g_cntA, &g_genA, GRID, &myA);

    // ======== split phase: vector recurrence (blocks 0..VB-1) || stage-1 GEMM ========
    if (bid < VB) {
        const int gw = bid * (NTHREADS / 32) + wid;         // 0..VB*8-1
        const int VW = VB * (NTHREADS / 32);

        auto do_update = [&](bool first) {
            for (int r = gw; r < MEMD + OUTD; r += VW) {
                const float* W = (r < MEMD) ? (p.W_enc + (size_t)r * HID)
                                            : (p.w_ho + (size_t)(r - MEMD) * HID);
                float s = 0.f;
                #pragma unroll
                for (int j = 0; j < 8; j++) {
                    int k = lane + j * 32;
                    float4 hv = __ldcg((const float4*)g_hid_v + k);
                    s += dot4(hv, *((const float4*)W + k));
                }
                s = warp_sum(s);
                if (lane == 0) {
                    if (r < MEMD) {
                        float e = tanhf(s + p.b_enc[r]);
                        float w = __ldcg(&g_wg_v[r]);
                        float m = first ? (w * e) : ((1.0f - w) * __ldcg(&g_mem_v[r]) + w * e);
                        __stcg(&g_mem_v[r], m);
                    } else {
                        __stcg(&g_out_v[r - MEMD], s);
                    }
                }
            }
        };
        auto do_gates = [&](bool constants) {
            for (int h = gw; h < HID; h += VW) {
                const float4* Wbi = (const float4*)(p.W_rinp + (size_t)h * OUTD);
                const float4* Wig = (const float4*)(p.W_rig  + (size_t)h * OUTD);
                const float4* Wrg = (const float4*)(p.W_rrg  + (size_t)h * OUTD);
                const float4* Wwg = (const float4*)(p.W_rwg  + (size_t)h * OUTD);
                const float4* Mig = (const float4*)(p.W_mig  + (size_t)h * MEMD);
                const float4* Mrg = (const float4*)(p.W_mrg  + (size_t)h * MEMD);
                const float4* Mwg = (const float4*)(p.W_mwg  + (size_t)h * MEMD);
                float s_bi = 0.f, s_ig = 0.f, s_rg = 0.f, s_wg = 0.f;
                #pragma unroll
                for (int j = 0; j < 4; j++) {
                    int k = lane + j * 32;
                    float4 o = __ldcg((const float4*)g_out_v + k);
                    s_bi += dot4(o, Wbi[k]);
                    s_ig += dot4(o, Wig[k]);
                    s_rg += dot4(o, Wrg[k]);
                    if (!constants) s_wg += dot4(o, Wwg[k]);
                }
                #pragma unroll
                for (int j = 0; j < 8; j++) {
                    int k = lane + j * 32;
                    float4 m = __ldcg((const float4*)g_mem_v + k);
                    s_ig += dot4(m, Mig[k]);
                    s_rg += dot4(m, Mrg[k]);
                    if (!constants) s_wg += dot4(m, Mwg[k]);
                }
                s_bi = warp_sum(s_bi); s_ig = warp_sum(s_ig); s_rg = warp_sum(s_rg);
                if (!constants) s_wg = warp_sum(s_wg);
                if (lane == 0) {
                    float pbi = s_bi + p.b_inp[h] + p.b_rinp[h];
                    float pig = s_ig + p.b_ig[h] + p.b_mig[h] + p.b_rig[h];
                    float prg = s_rg + p.b_rg[h] + p.b_mrg[h] + p.b_rrg[h];
                    if (!constants) {
                        float pwg = s_wg + p.b_wg[h] + p.b_mwg[h] + p.b_rwg[h];
                        __stcg(&g_prod_v[h],  sigf(pbi) * sigf(pig));
                        __stcg(&g_rgmem_v[h], sigf(prg) * __ldcg(&g_mem_v[h]));
                        __stcg(&g_wg_v[h],    sigf(pwg));
                    } else {
                        __stcg(&g_c_inp[h], pbi);
                        __stcg(&g_c_ig[h],  pig);
                        __stcg(&g_c_rg[h],  prg);
                    }
                }
            }
        };

        do_update(true);                       // step 0: mem = wg*tanh(enc), out = hid@w_ho^T
        gbar(&g_cntB, &g_genB, VB, &myB);
        for (int s = 1; s <= 3; s++) {
            do_gates(false);
            gbar(&g_cntB, &g_genB, VB, &myB);
            for (int h = gw; h < HID; h += VW) {
                const float4* Wd = (const float4*)(p.W_dec + (size_t)h * MEMD);
                float s2 = 0.f;
                #pragma unroll
                for (int j = 0; j < 8; j++) {
                    int k = lane + j * 32;
                    float4 rg = __ldcg((const float4*)g_rgmem_v + k);
                    s2 += dot4(rg, Wd[k]);
                }
                s2 = warp_sum(s2);
                if (lane == 0)
                    __stcg(&g_hid_v[h], s2 + p.b_dec[h] + __ldcg(&g_prod_v[h]));
            }
            gbar(&g_cntB, &g_genB, VB, &myB);
            do_update(false);
            gbar(&g_cntB, &g_genB, VB, &myB);
        }
        do_gates(true);                        // step-4 batch-uniform constants
    }
    // stage-1 GEMM: all non-vector blocks now; vector blocks join when done
    for (;;) {
        if (tid == 0) s_tk = atomicAdd(&g_t1, 1);
        __syncthreads();
        unsigned t = s_tk;
        if (t >= 768u) break;
        int mat = (int)(t >> 8);
        int rem = (int)(t & 255u);
        int m0 = (rem & 31) * TM, n0 = (rem >> 5) * TN;
        const float* B = (mat == 0) ? g_wb_inp : ((mat == 1) ? g_wb_ig : g_wb_rg);
        float* C = (mat == 0) ? &g_pre[0][0] : ((mat == 1) ? &g_pre[1][0] : &g_pre[2][0]);
        gemm_tile<0, 0>(smem, smb, tid, g_xT, B, C, IN_DIM, HID, m0, n0, nullptr, nullptr);
    }
    gbar(&g_cntA, &g_genA, GRID, &myA);

    // ======== gate elementwise (all blocks) ========
    for (size_t i = (size_t)bid * NTHREADS + tid; i < (size_t)BATCH * HID / 4;
         i += (size_t)GRID * NTHREADS) {
        size_t idx = i * 4;
        int h = (int)(idx & (HID - 1));
        float4 ci = *(const float4*)&g_c_inp[h];
        float4 cg = *(const float4*)&g_c_ig[h];
        float4 cr = *(const float4*)&g_c_rg[h];
        float4 mv = *(const float4*)&g_mem_v[h];
        float4 pi = *(const float4*)&g_pre[0][idx];
        float4 pg = *(const float4*)&g_pre[1][idx];
        float4 pr = *(const float4*)&g_pre[2][idx];
        float4 o1, o2;
        o1.x = sigf(pi.x + ci.x) * sigf(pg.x + cg.x);
        o1.y = sigf(pi.y + ci.y) * sigf(pg.y + cg.y);
        o1.z = sigf(pi.z + ci.z) * sigf(pg.z + cg.z);
        o1.w = sigf(pi.w + ci.w) * sigf(pg.w + cg.w);
        o2.x = rnd_tf32(sigf(pr.x + cr.x) * mv.x);
        o2.y = rnd_tf32(sigf(pr.y + cr.y) * mv.y);
        o2.z = rnd_tf32(sigf(pr.z + cr.z) * mv.z);
        o2.w = rnd_tf32(sigf(pr.w + cr.w) * mv.w);
        *(float4*)&g_pre[0][idx] = o1;     // prod -> addm for decoder epilogue
        *(float4*)&g_rgm[idx]    = o2;     // tf32-rounded decoder A operand
    }
    gbar(&g_cntA, &g_genA, GRID, &myA);

    // ======== decoder GEMM: hid = rgm @ Wb_dec^T + b_dec + prod (256 tiles) ========
    for (;;) {
        if (tid == 0) s_tk = atomicAdd(&g_t2, 1);
        __syncthreads();
        unsigned t = s_tk;
        if (t >= 256u) break;
        int m0 = ((int)t & 31) * TM, n0 = ((int)t >> 5) * TN;
        gemm_tile<1, 1>(smem, smb, tid, g_rgm, g_wb_dec, g_hid, MEMD, HID, m0, n0,
                        p.b_dec, &g_pre[0][0]);
    }
    gbar(&g_cntA, &g_genA, GRID, &myA);

    // ======== final GEMM: out = hid @ Wb_ho^T -> d_out (128 tiles) ========
    for (;;) {
        if (tid == 0) s_tk = atomicAdd(&g_t3, 1);
        __syncthreads();
        unsigned t = s_tk;
        if (t >= 128u) break;
        int m0 = ((int)t & 31) * TM, n0 = ((int)t >> 5) * TN;
        gemm_tile<0, 0>(smem, smb, tid, g_hid, g_wb_ho, dout, HID, OUTD, m0, n0,
                        nullptr, nullptr);
    }
}

// ---------------- launch ----------------
extern "C" void kernel_launch(void* const* d_in, const int* in_sizes, int n_in,
                              void* d_out, int out_size) {
    P p;
    const float** f = (const float**)&p;
    for (int i = 0; i < 28; i++) f[i] = (const float*)d_in[i];

    cudaFuncSetAttribute(k_main, cudaFuncAttributeMaxDynamicSharedMemorySize, SMEM_BYTES);
    k_main<<<GRID, NTHREADS, SMEM_BYTES>>>(p, (float*)d_out);
}

// round 9
// speedup vs baseline: 1.1459x; 1.1459x over previous
#include <cuda_runtime.h>
#include <math.h>
#include <stdint.h>

#define IN_DIM 512
#define HID    1024
#define MEMD   1024
#define OUTD   512
#define BATCH  4096

#define TM 128
#define TN 128
#define KC 32
#define GEMM_THREADS 256
#define CH_FLOATS (128 * 32)
#define CH_BYTES  (CH_FLOATS * 4)            // 16384
#define SMEM_BYTES_G (6 * CH_BYTES)          // 98304, 2 CTAs/SM
#define GEMM_GRID 296

#define VGRID 296
#define VTHREADS 256

// ---------------- device scratch ----------------
__device__ __align__(16) float g_xT [(size_t)BATCH * IN_DIM];
__device__ __align__(16) float g_pre[3][(size_t)BATCH * HID];
__device__ __align__(16) float g_rgm[(size_t)BATCH * MEMD];
__device__ __align__(16) float g_hid[(size_t)BATCH * HID];

// vector state
__device__ __align__(16) float g_out_v[OUTD];
__device__ __align__(16) float g_mem_v[MEMD];
__device__ __align__(16) float g_prod_v[HID];
__device__ __align__(16) float g_rgmem_v[MEMD];
__device__ __align__(16) float g_wg_v[MEMD];
__device__ __align__(16) float g_hid_v[HID];
__device__ __align__(16) float g_c_inp[HID];
__device__ __align__(16) float g_c_ig[HID];
__device__ __align__(16) float g_c_rg[MEMD];

// software grid barrier (g_cnt returns to 0; g_gen monotonic)
__device__ unsigned g_cnt = 0;
__device__ unsigned g_gen = 0;

struct P {
    const float *input;
    const float *W_ig, *b_ig, *W_rig, *b_rig, *W_mig, *b_mig;
    const float *W_inp, *b_inp, *W_rinp, *b_rinp;
    const float *W_rg, *b_rg, *W_rrg, *b_rrg, *W_mrg, *b_mrg;
    const float *W_dec, *b_dec;
    const float *W_wg, *b_wg, *W_rwg, *b_rwg, *W_mwg, *b_mwg;
    const float *W_enc, *b_enc, *w_ho;
};

__device__ __forceinline__ float sigf(float x) { return 1.0f / (1.0f + expf(-x)); }
__device__ __forceinline__ float warp_sum(float v) {
    #pragma unroll
    for (int o = 16; o; o >>= 1) v += __shfl_xor_sync(0xFFFFFFFFu, v, o);
    return v;
}
__device__ __forceinline__ float dot4(float4 a, float4 b) {
    return a.x * b.x + a.y * b.y + a.z * b.z + a.w * b.w;
}

__device__ __forceinline__ void mma1688(float* c, const uint32_t* a, const uint32_t* b) {
    asm volatile(
        "mma.sync.aligned.m16n8k8.row.col.f32.tf32.tf32.f32 "
        "{%0,%1,%2,%3}, {%4,%5,%6,%7}, {%8,%9}, {%0,%1,%2,%3};"
        : "+f"(c[0]), "+f"(c[1]), "+f"(c[2]), "+f"(c[3])
        : "r"(a[0]), "r"(a[1]), "r"(a[2]), "r"(a[3]), "r"(b[0]), "r"(b[1]));
}
__device__ __forceinline__ void cp16(uint32_t dst, const void* src) {
    asm volatile("cp.async.cg.shared.global [%0], [%1], 16;" :: "r"(dst), "l"(src));
}
#define CP_COMMIT() asm volatile("cp.async.commit_group;" ::: "memory")
#define CP_WAIT(n)  asm volatile("cp.async.wait_group %0;" :: "n"(n) : "memory")
__device__ __forceinline__ uint32_t smem_u32(const void* p) {
    uint32_t a;
    asm("{ .reg .u64 t; cvta.to.shared.u64 t, %1; cvt.u32.u64 %0, t; }" : "=r"(a) : "l"(p));
    return a;
}

// ---------------- grid-wide barrier (all VGRID blocks co-resident) ----------------
__device__ __forceinline__ void gsync(unsigned* mygen) {
    __syncthreads();
    if (threadIdx.x == 0) {
        __threadfence();
        unsigned a = atomicAdd(&g_cnt, 1);
        if (a == VGRID - 1) {
            g_cnt = 0;
            __threadfence();
            atomicAdd(&g_gen, 1);
        } else {
            while (*(volatile unsigned*)&g_gen == *mygen) __nanosleep(64);
        }
        __threadfence();
    }
    __syncthreads();
    (*mygen)++;
}

// ---------------- persistent: transpose + vector recurrence (raw fp32, no prep) ----------------
__global__ __launch_bounds__(VTHREADS) void k_vec(P p) {
    __shared__ float tile[32][33];
    const int tid = threadIdx.x, wid = tid >> 5, lane = tid & 31;
    const int gw = blockIdx.x * (VTHREADS / 32) + wid;
    const int VW = VGRID * (VTHREADS / 32);
    unsigned mygen = *(volatile unsigned*)&g_gen;

    // ---- transpose: input [512,4096] -> g_xT [4096,512] (raw fp32) ----
    {
        const int tx = tid & 31, ty8 = tid >> 5;
        for (int t = blockIdx.x; t < 2048; t += VGRID) {
            int bx = (t & 127) * 32;
            int by = (t >> 7) * 32;
            #pragma unroll
            for (int j = ty8; j < 32; j += 8)
                tile[j][tx] = p.input[(size_t)(by + j) * BATCH + bx + tx];
            __syncthreads();
            #pragma unroll
            for (int j = ty8; j < 32; j += 8)
                g_xT[(size_t)(bx + j) * IN_DIM + by + tx] = tile[tx][j];
            __syncthreads();
        }
    }

    // ---- step 0 elementwise: out=mem=0 -> gates are bias-only ----
    for (int h = blockIdx.x * VTHREADS + tid; h < HID; h += VGRID * VTHREADS) {
        float pbi = p.b_inp[h] + p.b_rinp[h];
        float pig = p.b_ig[h] + p.b_mig[h] + p.b_rig[h];
        float pwg = p.b_wg[h] + p.b_mwg[h] + p.b_rwg[h];
        __stcg(&g_hid_v[h], p.b_dec[h] + sigf(pbi) * sigf(pig));
        __stcg(&g_wg_v[h], sigf(pwg));
    }
    gsync(&mygen);

    auto do_update = [&](bool first) {
        for (int r = gw; r < MEMD + OUTD; r += VW) {
            const float* W = (r < MEMD) ? (p.W_enc + (size_t)r * HID)
                                        : (p.w_ho + (size_t)(r - MEMD) * HID);
            float s = 0.f;
            #pragma unroll
            for (int j = 0; j < 8; j++) {
                int k = lane + j * 32;
                float4 hv = __ldcg((const float4*)g_hid_v + k);
                s += dot4(hv, *((const float4*)W + k));
            }
            s = warp_sum(s);
            if (lane == 0) {
                if (r < MEMD) {
                    float e = tanhf(s + p.b_enc[r]);
                    float w = __ldcg(&g_wg_v[r]);
                    float m = first ? (w * e) : ((1.0f - w) * __ldcg(&g_mem_v[r]) + w * e);
                    __stcg(&g_mem_v[r], m);
                } else {
                    __stcg(&g_out_v[r - MEMD], s);
                }
            }
        }
    };

    do_update(true);
    gsync(&mygen);

    auto do_gates = [&](bool constants) {
        for (int h = gw; h < HID; h += VW) {
            const float4* Wbi = (const float4*)(p.W_rinp + (size_t)h * OUTD);
            const float4* Wig = (const float4*)(p.W_rig  + (size_t)h * OUTD);
            const float4* Wrg = (const float4*)(p.W_rrg  + (size_t)h * OUTD);
            const float4* Wwg = (const float4*)(p.W_rwg  + (size_t)h * OUTD);
            const float4* Mig = (const float4*)(p.W_mig  + (size_t)h * MEMD);
            const float4* Mrg = (const float4*)(p.W_mrg  + (size_t)h * MEMD);
            const float4* Mwg = (const float4*)(p.W_mwg  + (size_t)h * MEMD);
            float s_bi = 0.f, s_ig = 0.f, s_rg = 0.f, s_wg = 0.f;
            #pragma unroll
            for (int j = 0; j < 4; j++) {
                int k = lane + j * 32;
                float4 o = __ldcg((const float4*)g_out_v + k);
                s_bi += dot4(o, Wbi[k]);
                s_ig += dot4(o, Wig[k]);
                s_rg += dot4(o, Wrg[k]);
                if (!constants) s_wg += dot4(o, Wwg[k]);
            }
            #pragma unroll
            for (int j = 0; j < 8; j++) {
                int k = lane + j * 32;
                float4 m = __ldcg((const float4*)g_mem_v + k);
                s_ig += dot4(m, Mig[k]);
                s_rg += dot4(m, Mrg[k]);
                if (!constants) s_wg += dot4(m, Mwg[k]);
            }
            s_bi = warp_sum(s_bi); s_ig = warp_sum(s_ig); s_rg = warp_sum(s_rg);
            if (!constants) s_wg = warp_sum(s_wg);
            if (lane == 0) {
                float pbi = s_bi + p.b_inp[h] + p.b_rinp[h];
                float pig = s_ig + p.b_ig[h] + p.b_mig[h] + p.b_rig[h];
                float prg = s_rg + p.b_rg[h] + p.b_mrg[h] + p.b_rrg[h];
                if (!constants) {
                    float pwg = s_wg + p.b_wg[h] + p.b_mwg[h] + p.b_rwg[h];
                    __stcg(&g_prod_v[h],  sigf(pbi) * sigf(pig));
                    __stcg(&g_rgmem_v[h], sigf(prg) * __ldcg(&g_mem_v[h]));
                    __stcg(&g_wg_v[h],    sigf(pwg));
                } else {
                    __stcg(&g_c_inp[h], pbi);
                    __stcg(&g_c_ig[h],  pig);
                    __stcg(&g_c_rg[h],  prg);
                }
            }
        }
    };

    for (int s = 1; s <= 3; s++) {
        do_gates(false);
        gsync(&mygen);
        for (int h = gw; h < HID; h += VW) {
            const float4* Wd = (const float4*)(p.W_dec + (size_t)h * MEMD);
            float s2 = 0.f;
            #pragma unroll
            for (int j = 0; j < 8; j++) {
                int k = lane + j * 32;
                float4 rg = __ldcg((const float4*)g_rgmem_v + k);
                s2 += dot4(rg, Wd[k]);
            }
            s2 = warp_sum(s2);
            if (lane == 0)
                __stcg(&g_hid_v[h], s2 + p.b_dec[h] + __ldcg(&g_prod_v[h]));
        }
        gsync(&mygen);
        do_update(false);
        gsync(&mygen);
    }

    do_gates(true);   // step-4 batch-uniform constants
}

// ---------------- persistent tf32 GEMM, 3-stage cp.async, XOR-swizzled, 2 CTAs/SM ----------------
// C[M,N] = A[M,K] @ B[N,K]^T ; operands are RAW fp32 (HW truncates to tf32 in the MMA).
// Swizzle: 128B rows, 16B granule q stored at q ^ (row & 7). One __syncthreads per chunk.
template <int MODE>
__global__ __launch_bounds__(GEMM_THREADS, 2) void k_tgemm(
    const float* __restrict__ A,
    const float* __restrict__ B0, const float* __restrict__ B1, const float* __restrict__ B2,
    float* __restrict__ C0, float* __restrict__ C1, float* __restrict__ C2,
    int K, int ldC, int ntm, int ntn, int nmat,
    const float* __restrict__ bias, const float* __restrict__ addm)
{
    extern __shared__ float smem[];
    const uint32_t smb = smem_u32(smem);
    const int tid = threadIdx.x, wid = tid >> 5, lane = tid & 31;
    const int g = lane >> 2, t4 = lane & 3;
    const int wm = (wid >> 2) * 64, wn = (wid & 3) * 32;
    const int nc = K / KC;
    const int tpm = ntm * ntn;
    const int ntiles = nmat * tpm;

    const int ld_r[4] = { tid >> 3, (256 + tid) >> 3, (512 + tid) >> 3, (768 + tid) >> 3 };
    const int ld_q = tid & 7;

    for (int t = blockIdx.x; t < ntiles; t += gridDim.x) {
        const int mat = t / tpm, rem = t % tpm;
        const int m0 = (rem % ntm) * TM, n0 = (rem / ntm) * TN;
        const float* B = (mat == 0) ? B0 : ((mat == 1) ? B1 : B2);
        float* C = (mat == 0) ? C0 : ((mat == 1) ? C1 : C2);

        float acc[4][4][4];
        #pragma unroll
        for (int i = 0; i < 4; i++)
            #pragma unroll
            for (int j = 0; j < 4; j++)
                #pragma unroll
                for (int q = 0; q < 4; q++) acc[i][j][q] = 0.f;

        auto issue = [&](int k0, int buf) {
            uint32_t ab = smb + buf * CH_BYTES;
            uint32_t bb = smb + (3 + buf) * CH_BYTES;
            #pragma unroll
            for (int j = 0; j < 4; j++) {
                int r = ld_r[j];
                uint32_t dst = (uint32_t)((r * 8 + (ld_q ^ (r & 7))) * 16);
                cp16(ab + dst, A + (size_t)(m0 + r) * K + k0 + ld_q * 4);
                cp16(bb + dst, B + (size_t)(n0 + r) * K + k0 + ld_q * 4);
            }
            CP_COMMIT();
        };
        auto compute = [&](int buf) {
            const uint32_t* as_ = (const uint32_t*)(smem + buf * CH_FLOATS);
            const uint32_t* bs_ = (const uint32_t*)(smem + (3 + buf) * CH_FLOATS);
            #pragma unroll
            for (int ks = 0; ks < 4; ks++) {
                const int c0 = ((2 * ks) ^ g) * 4 + t4;
                const int c1 = c0 ^ 4;
                uint32_t af[4][4], bf[4][2];
                #pragma unroll
                for (int mt = 0; mt < 4; mt++) {
                    int m = wm + mt * 16 + g;
                    af[mt][0] = as_[m * 32 + c0];
                    af[mt][1] = as_[(m + 8) * 32 + c0];
                    af[mt][2] = as_[m * 32 + c1];
                    af[mt][3] = as_[(m + 8) * 32 + c1];
                }
                #pragma unroll
                for (int nt = 0; nt < 4; nt++) {
                    int n = wn + nt * 8 + g;
                    bf[nt][0] = bs_[n * 32 + c0];
                    bf[nt][1] = bs_[n * 32 + c1];
                }
                #pragma unroll
                for (int mt = 0; mt < 4; mt++)
                    #pragma unroll
                    for (int nt = 0; nt < 4; nt++)
                        mma1688(acc[mt][nt], af[mt], bf[nt]);
            }
        };

        issue(0, 0);
        issue(KC, 1);
        for (int c = 0; c < nc; c++) {
            CP_WAIT(1);
            __syncthreads();
            if (c + 2 < nc) issue((c + 2) * KC, (c + 2) % 3);
            compute(c % 3);
        }
        __syncthreads();

        // ---- epilogue: smem staging -> coalesced float4 stores ----
        float* stg = smem;
        #pragma unroll
        for (int mt = 0; mt < 4; mt++) {
            #pragma unroll
            for (int nt = 0; nt < 4; nt++) {
                int rr = wm + mt * 16 + g;
                int cc = wn + nt * 8 + t4 * 2;
                *(float2*)(stg + rr * 132 + cc)       = make_float2(acc[mt][nt][0], acc[mt][nt][1]);
                *(float2*)(stg + (rr + 8) * 132 + cc) = make_float2(acc[mt][nt][2], acc[mt][nt][3]);
            }
        }
        __syncthreads();
        #pragma unroll
        for (int j = 0; j < 16; j++) {
            int s = j * GEMM_THREADS + tid;
            int r = s >> 5, cq = s & 31;
            int m = m0 + r, n = n0 + cq * 4;
            float4 v = *(float4*)(stg + r * 132 + cq * 4);
            if (MODE == 1) {
                const float4 bv = *(const float4*)(bias + n);
                const float4 av = *(const float4*)(addm + (size_t)m * ldC + n);
                v.x += bv.x + av.x; v.y += bv.y + av.y;
                v.z += bv.z + av.z; v.w += bv.w + av.w;
            }
            *(float4*)(C + (size_t)m * ldC + n) = v;
        }
        __syncthreads();
    }
}

// ---------------- fused gate elementwise (step 4), [B, F] layout ----------------
__global__ void k_gate_elem() {
    size_t idx = ((size_t)blockIdx.x * blockDim.x + threadIdx.x) * 4;
    int h = (int)(idx & (HID - 1));
    float4 ci = *(const float4*)&g_c_inp[h];
    float4 cg = *(const float4*)&g_c_ig[h];
    float4 cr = *(const float4*)&g_c_rg[h];
    float4 mv = *(const float4*)&g_mem_v[h];
    float4 pi = *(const float4*)&g_pre[0][idx];
    float4 pg = *(const float4*)&g_pre[1][idx];
    float4 pr = *(const float4*)&g_pre[2][idx];
    float4 o1, o2;
    o1.x = sigf(pi.x + ci.x) * sigf(pg.x + cg.x);
    o1.y = sigf(pi.y + ci.y) * sigf(pg.y + cg.y);
    o1.z = sigf(pi.z + ci.z) * sigf(pg.z + cg.z);
    o1.w = sigf(pi.w + ci.w) * sigf(pg.w + cg.w);
    o2.x = sigf(pr.x + cr.x) * mv.x;
    o2.y = sigf(pr.y + cr.y) * mv.y;
    o2.z = sigf(pr.z + cr.z) * mv.z;
    o2.w = sigf(pr.w + cr.w) * mv.w;
    *(float4*)&g_pre[0][idx] = o1;   // prod -> addm for decoder epilogue
    *(float4*)&g_rgm[idx]    = o2;   // raw fp32 decoder A operand (HW truncates)
}

// ---------------- launch ----------------
extern "C" void kernel_launch(void* const* d_in, const int* in_sizes, int n_in,
                              void* d_out, int out_size) {
    P p;
    const float** f = (const float**)&p;
    for (int i = 0; i < 28; i++) f[i] = (const float*)d_in[i];

    float *xT, *pre, *rgm, *hid;
    cudaGetSymbolAddress((void**)&xT,  g_xT);
    cudaGetSymbolAddress((void**)&pre, g_pre);
    cudaGetSymbolAddress((void**)&rgm, g_rgm);
    cudaGetSymbolAddress((void**)&hid, g_hid);
    float* pre0 = pre;
    float* pre1 = pre + (size_t)BATCH * HID;
    float* pre2 = pre + (size_t)2 * BATCH * HID;

    cudaFuncSetAttribute(k_tgemm<0>, cudaFuncAttributeMaxDynamicSharedMemorySize, SMEM_BYTES_G);
    cudaFuncSetAttribute(k_tgemm<1>, cudaFuncAttributeMaxDynamicSharedMemorySize, SMEM_BYTES_G);

    // 1. transpose + vector recurrence + step-4 constants (no weight prep needed)
    k_vec<<<VGRID, VTHREADS>>>(p);

    // 2. stage-1: three fused GEMMs  pre_i[B,1024] = xT @ W_i^T  (768 tiles, raw weights)
    k_tgemm<0><<<GEMM_GRID, GEMM_THREADS, SMEM_BYTES_G>>>(
        xT, p.W_inp, p.W_ig, p.W_rg, pre0, pre1, pre2,
        IN_DIM, HID, BATCH / TM, HID / TN, 3, nullptr, nullptr);

    // 3. fused sigmoid gates
    k_gate_elem<<<(int)(((size_t)BATCH * HID / 4) / 256), 256>>>();

    // 4. decoder: hid[B,1024] = rgm @ W_dec^T + b_dec + prod  (256 tiles)
    k_tgemm<1><<<GEMM_GRID, GEMM_THREADS, SMEM_BYTES_G>>>(
        rgm, p.W_dec, nullptr, nullptr, hid, nullptr, nullptr,
        MEMD, HID, BATCH / TM, HID / TN, 1, p.b_dec, pre0);

    // 5. out[B,512] = hid @ w_ho^T -> d_out  (128 tiles)
    k_tgemm<0><<<GEMM_GRID, GEMM_THREADS, SMEM_BYTES_G>>>(
        hid, p.w_ho, nullptr, nullptr, (float*)d_out, nullptr, nullptr,
        HID, OUTD, BATCH / TM, OUTD / TN, 1, nullptr, nullptr);
}

// round 10
// speedup vs baseline: 1.2074x; 1.0536x over previous
#include <cuda_runtime.h>
#include <math.h>
#include <stdint.h>

#define IN_DIM 512
#define HID    1024
#define MEMD   1024
#define OUTD   512
#define BATCH  4096

#define TM 128
#define TN 128
#define KC 32
#define GEMM_THREADS 256
#define CH_FLOATS (128 * 32)
#define CH_BYTES  (CH_FLOATS * 4)            // 16384
#define SMEM_BYTES_G (6 * CH_BYTES)          // 98304, 2 CTAs/SM
#define GEMM_GRID 296

#define VGRID 296
#define VTHREADS 256

// ---------------- device scratch ----------------
__device__ __align__(16) float g_xT [(size_t)BATCH * IN_DIM];
__device__ __align__(16) float g_pre[3][(size_t)BATCH * HID];
__device__ __align__(16) float g_rgm[(size_t)BATCH * MEMD];
__device__ __align__(16) float g_hid[(size_t)BATCH * HID];

// vector state
__device__ __align__(16) float g_out_v[OUTD];
__device__ __align__(16) float g_mem_v[MEMD];
__device__ __align__(16) float g_prod_v[HID];
__device__ __align__(16) float g_rgmem_v[MEMD];
__device__ __align__(16) float g_wg_v[MEMD];
__device__ __align__(16) float g_hid_v[HID];
__device__ __align__(16) float g_c_inp[HID];
__device__ __align__(16) float g_c_ig[HID];
__device__ __align__(16) float g_c_rg[MEMD];

// software grid barrier (g_cnt returns to 0; g_gen monotonic)
__device__ unsigned g_cnt = 0;
__device__ unsigned g_gen = 0;

struct P {
    const float *input;
    const float *W_ig, *b_ig, *W_rig, *b_rig, *W_mig, *b_mig;
    const float *W_inp, *b_inp, *W_rinp, *b_rinp;
    const float *W_rg, *b_rg, *W_rrg, *b_rrg, *W_mrg, *b_mrg;
    const float *W_dec, *b_dec;
    const float *W_wg, *b_wg, *W_rwg, *b_rwg, *W_mwg, *b_mwg;
    const float *W_enc, *b_enc, *w_ho;
};

__device__ __forceinline__ float sigf(float x) { return 1.0f / (1.0f + expf(-x)); }
__device__ __forceinline__ float warp_sum(float v) {
    #pragma unroll
    for (int o = 16; o; o >>= 1) v += __shfl_xor_sync(0xFFFFFFFFu, v, o);
    return v;
}
__device__ __forceinline__ float dot4(float4 a, float4 b) {
    return a.x * b.x + a.y * b.y + a.z * b.z + a.w * b.w;
}

__device__ __forceinline__ void mma1688(float* c, const uint32_t* a, const uint32_t* b) {
    asm volatile(
        "mma.sync.aligned.m16n8k8.row.col.f32.tf32.tf32.f32 "
        "{%0,%1,%2,%3}, {%4,%5,%6,%7}, {%8,%9}, {%0,%1,%2,%3};"
        : "+f"(c[0]), "+f"(c[1]), "+f"(c[2]), "+f"(c[3])
        : "r"(a[0]), "r"(a[1]), "r"(a[2]), "r"(a[3]), "r"(b[0]), "r"(b[1]));
}
__device__ __forceinline__ void ldsm4(uint32_t* r, uint32_t addr) {
    asm volatile("ldmatrix.sync.aligned.m8n8.x4.shared.b16 {%0,%1,%2,%3}, [%4];"
        : "=r"(r[0]), "=r"(r[1]), "=r"(r[2]), "=r"(r[3]) : "r"(addr));
}
__device__ __forceinline__ void cp16(uint32_t dst, const void* src) {
    asm volatile("cp.async.cg.shared.global [%0], [%1], 16;" :: "r"(dst), "l"(src));
}
#define CP_COMMIT() asm volatile("cp.async.commit_group;" ::: "memory")
#define CP_WAIT(n)  asm volatile("cp.async.wait_group %0;" :: "n"(n) : "memory")
__device__ __forceinline__ uint32_t smem_u32(const void* p) {
    uint32_t a;
    asm("{ .reg .u64 t; cvta.to.shared.u64 t, %1; cvt.u32.u64 %0, t; }" : "=r"(a) : "l"(p));
    return a;
}

// ---------------- grid-wide barrier (all VGRID blocks co-resident) ----------------
__device__ __forceinline__ void gsync(unsigned* mygen) {
    __syncthreads();
    if (threadIdx.x == 0) {
        __threadfence();
        unsigned a = atomicAdd(&g_cnt, 1);
        if (a == VGRID - 1) {
            g_cnt = 0;
            __threadfence();
            atomicAdd(&g_gen, 1);
        } else {
            while (*(volatile unsigned*)&g_gen == *mygen) __nanosleep(64);
        }
        __threadfence();
    }
    __syncthreads();
    (*mygen)++;
}

// ---------------- persistent: transpose + vector recurrence (raw fp32) ----------------
__global__ __launch_bounds__(VTHREADS) void k_vec(P p) {
    __shared__ float tile[32][33];
    const int tid = threadIdx.x, wid = tid >> 5, lane = tid & 31;
    const int gw = blockIdx.x * (VTHREADS / 32) + wid;
    const int VW = VGRID * (VTHREADS / 32);
    unsigned mygen = *(volatile unsigned*)&g_gen;

    // ---- transpose: input [512,4096] -> g_xT [4096,512] ----
    {
        const int tx = tid & 31, ty8 = tid >> 5;
        for (int t = blockIdx.x; t < 2048; t += VGRID) {
            int bx = (t & 127) * 32;
            int by = (t >> 7) * 32;
            #pragma unroll
            for (int j = ty8; j < 32; j += 8)
                tile[j][tx] = p.input[(size_t)(by + j) * BATCH + bx + tx];
            __syncthreads();
            #pragma unroll
            for (int j = ty8; j < 32; j += 8)
                g_xT[(size_t)(bx + j) * IN_DIM + by + tx] = tile[tx][j];
            __syncthreads();
        }
    }

    // ---- step 0 elementwise: out=mem=0 -> gates are bias-only ----
    for (int h = blockIdx.x * VTHREADS + tid; h < HID; h += VGRID * VTHREADS) {
        float pbi = p.b_inp[h] + p.b_rinp[h];
        float pig = p.b_ig[h] + p.b_mig[h] + p.b_rig[h];
        float pwg = p.b_wg[h] + p.b_mwg[h] + p.b_rwg[h];
        __stcg(&g_hid_v[h], p.b_dec[h] + sigf(pbi) * sigf(pig));
        __stcg(&g_wg_v[h], sigf(pwg));
    }
    gsync(&mygen);

    auto do_update = [&](bool first) {
        for (int r = gw; r < MEMD + OUTD; r += VW) {
            const float* W = (r < MEMD) ? (p.W_enc + (size_t)r * HID)
                                        : (p.w_ho + (size_t)(r - MEMD) * HID);
            float s = 0.f;
            #pragma unroll
            for (int j = 0; j < 8; j++) {
                int k = lane + j * 32;
                float4 hv = __ldcg((const float4*)g_hid_v + k);
                s += dot4(hv, *((const float4*)W + k));
            }
            s = warp_sum(s);
            if (lane == 0) {
                if (r < MEMD) {
                    float e = tanhf(s + p.b_enc[r]);
                    float w = __ldcg(&g_wg_v[r]);
                    float m = first ? (w * e) : ((1.0f - w) * __ldcg(&g_mem_v[r]) + w * e);
                    __stcg(&g_mem_v[r], m);
                } else {
                    __stcg(&g_out_v[r - MEMD], s);
                }
            }
        }
    };

    do_update(true);
    gsync(&mygen);

    auto do_gates = [&](bool constants) {
        for (int h = gw; h < HID; h += VW) {
            const float4* Wbi = (const float4*)(p.W_rinp + (size_t)h * OUTD);
            const float4* Wig = (const float4*)(p.W_rig  + (size_t)h * OUTD);
            const float4* Wrg = (const float4*)(p.W_rrg  + (size_t)h * OUTD);
            const float4* Wwg = (const float4*)(p.W_rwg  + (size_t)h * OUTD);
            const float4* Mig = (const float4*)(p.W_mig  + (size_t)h * MEMD);
            const float4* Mrg = (const float4*)(p.W_mrg  + (size_t)h * MEMD);
            const float4* Mwg = (const float4*)(p.W_mwg  + (size_t)h * MEMD);
            float s_bi = 0.f, s_ig = 0.f, s_rg = 0.f, s_wg = 0.f;
            #pragma unroll
            for (int j = 0; j < 4; j++) {
                int k = lane + j * 32;
                float4 o = __ldcg((const float4*)g_out_v + k);
                s_bi += dot4(o, Wbi[k]);
                s_ig += dot4(o, Wig[k]);
                s_rg += dot4(o, Wrg[k]);
                if (!constants) s_wg += dot4(o, Wwg[k]);
            }
            #pragma unroll
            for (int j = 0; j < 8; j++) {
                int k = lane + j * 32;
                float4 m = __ldcg((const float4*)g_mem_v + k);
                s_ig += dot4(m, Mig[k]);
                s_rg += dot4(m, Mrg[k]);
                if (!constants) s_wg += dot4(m, Mwg[k]);
            }
            s_bi = warp_sum(s_bi); s_ig = warp_sum(s_ig); s_rg = warp_sum(s_rg);
            if (!constants) s_wg = warp_sum(s_wg);
            if (lane == 0) {
                float pbi = s_bi + p.b_inp[h] + p.b_rinp[h];
                float pig = s_ig + p.b_ig[h] + p.b_mig[h] + p.b_rig[h];
                float prg = s_rg + p.b_rg[h] + p.b_mrg[h] + p.b_rrg[h];
                if (!constants) {
                    float pwg = s_wg + p.b_wg[h] + p.b_mwg[h] + p.b_rwg[h];
                    __stcg(&g_prod_v[h],  sigf(pbi) * sigf(pig));
                    __stcg(&g_rgmem_v[h], sigf(prg) * __ldcg(&g_mem_v[h]));
                    __stcg(&g_wg_v[h],    sigf(pwg));
                } else {
                    __stcg(&g_c_inp[h], pbi);
                    __stcg(&g_c_ig[h],  pig);
                    __stcg(&g_c_rg[h],  prg);
                }
            }
        }
    };

    for (int s = 1; s <= 3; s++) {
        do_gates(false);
        gsync(&mygen);
        for (int h = gw; h < HID; h += VW) {
            const float4* Wd = (const float4*)(p.W_dec + (size_t)h * MEMD);
            float s2 = 0.f;
            #pragma unroll
            for (int j = 0; j < 8; j++) {
                int k = lane + j * 32;
                float4 rg = __ldcg((const float4*)g_rgmem_v + k);
                s2 += dot4(rg, Wd[k]);
            }
            s2 = warp_sum(s2);
            if (lane == 0)
                __stcg(&g_hid_v[h], s2 + p.b_dec[h] + __ldcg(&g_prod_v[h]));
        }
        gsync(&mygen);
        do_update(false);
        gsync(&mygen);
    }

    do_gates(true);   // step-4 batch-uniform constants
}

// ---------------- persistent tf32 GEMM: 3-stage cp.async + ldmatrix fragments ----------------
// C[M,N] = A[M,K] @ B[N,K]^T ; raw fp32 operands (HW truncates to tf32).
// Swizzle: 16B granule q at q^(row&7). ldmatrix.x4 loads 4 fragment regs per issue.
template <int MODE>
__global__ __launch_bounds__(GEMM_THREADS, 2) void k_tgemm(
    const float* __restrict__ A,
    const float* __restrict__ B0, const float* __restrict__ B1, const float* __restrict__ B2,
    float* __restrict__ C0, float* __restrict__ C1, float* __restrict__ C2,
    int K, int ldC, int ntm, int ntn, int nmat,
    const float* __restrict__ bias, const float* __restrict__ addm)
{
    extern __shared__ float smem[];
    const uint32_t smb = smem_u32(smem);
    const int tid = threadIdx.x, wid = tid >> 5, lane = tid & 31;
    const int g = lane >> 2, t4 = lane & 3;
    const int wm = (wid >> 2) * 64, wn = (wid & 3) * 32;
    const int nc = K / KC;
    const int tpm = ntm * ntn;
    const int ntiles = nmat * tpm;

    // cp.async loader lanes
    const int ld_r[4] = { tid >> 3, (256 + tid) >> 3, (512 + tid) >> 3, (768 + tid) >> 3 };
    const int ld_q = tid & 7;

    // ldmatrix lane decomposition
    const int jm = lane >> 3, rr = lane & 7;
    const int hA = jm >> 1;                 // k-half for A matrices
    const int hB = jm & 1;                  // k-half for B matrices
    // row offsets (bytes; 128 B per row)
    const uint32_t aRowOff = (uint32_t)(wm + (jm & 1) * 8 + rr) * 128u;
    const uint32_t bRowOff = (uint32_t)(wn + (jm >> 1) * 8 + rr) * 128u;

    for (int t = blockIdx.x; t < ntiles; t += gridDim.x) {
        const int mat = t / tpm, rem = t % tpm;
        const int m0 = (rem % ntm) * TM, n0 = (rem / ntm) * TN;
        const float* B = (mat == 0) ? B0 : ((mat == 1) ? B1 : B2);
        float* C = (mat == 0) ? C0 : ((mat == 1) ? C1 : C2);

        float acc[4][4][4];
        #pragma unroll
        for (int i = 0; i < 4; i++)
            #pragma unroll
            for (int j = 0; j < 4; j++)
                #pragma unroll
                for (int q = 0; q < 4; q++) acc[i][j][q] = 0.f;

        auto issue = [&](int k0, int buf) {
            uint32_t ab = smb + buf * CH_BYTES;
            uint32_t bb = smb + (3 + buf) * CH_BYTES;
            #pragma unroll
            for (int j = 0; j < 4; j++) {
                int r = ld_r[j];
                uint32_t dst = (uint32_t)((r * 8 + (ld_q ^ (r & 7))) * 16);
                cp16(ab + dst, A + (size_t)(m0 + r) * K + k0 + ld_q * 4);
                cp16(bb + dst, B + (size_t)(n0 + r) * K + k0 + ld_q * 4);
            }
            CP_COMMIT();
        };
        auto compute = [&](int buf) {
            const uint32_t abase = smb + buf * CH_BYTES + aRowOff;
            const uint32_t bbase = smb + (3 + buf) * CH_BYTES + bRowOff;
            #pragma unroll
            for (int ks = 0; ks < 4; ks++) {
                const uint32_t qa = (uint32_t)(((2 * ks + hA) ^ rr) << 4);
                const uint32_t qb = (uint32_t)(((2 * ks + hB) ^ rr) << 4);
                uint32_t af[4][4], bf[8];
                #pragma unroll
                for (int mt = 0; mt < 4; mt++)
                    ldsm4(af[mt], abase + (uint32_t)(mt * 2048) + qa);
                ldsm4(bf,     bbase + qb);           // nt 0,1
                ldsm4(bf + 4, bbase + 2048u + qb);   // nt 2,3
                #pragma unroll
                for (int mt = 0; mt < 4; mt++)
                    #pragma unroll
                    for (int nt = 0; nt < 4; nt++)
                        mma1688(acc[mt][nt], af[mt], bf + nt * 2);
            }
        };

        issue(0, 0);
        issue(KC, 1);
        for (int c = 0; c < nc; c++) {
            CP_WAIT(1);
            __syncthreads();
            if (c + 2 < nc) issue((c + 2) * KC, (c + 2) % 3);
            compute(c % 3);
        }
        __syncthreads();

        // ---- epilogue: smem staging -> coalesced float4 stores ----
        float* stg = smem;
        #pragma unroll
        for (int mt = 0; mt < 4; mt++) {
            #pragma unroll
            for (int nt = 0; nt < 4; nt++) {
                int rrow = wm + mt * 16 + g;
                int cc = wn + nt * 8 + t4 * 2;
                *(float2*)(stg + rrow * 132 + cc)       = make_float2(acc[mt][nt][0], acc[mt][nt][1]);
                *(float2*)(stg + (rrow + 8) * 132 + cc) = make_float2(acc[mt][nt][2], acc[mt][nt][3]);
            }
        }
        __syncthreads();
        #pragma unroll
        for (int j = 0; j < 16; j++) {
            int s = j * GEMM_THREADS + tid;
            int r = s >> 5, cq = s & 31;
            int m = m0 + r, n = n0 + cq * 4;
            float4 v = *(float4*)(stg + r * 132 + cq * 4);
            if (MODE == 1) {
                const float4 bv = *(const float4*)(bias + n);
                const float4 av = *(const float4*)(addm + (size_t)m * ldC + n);
                v.x += bv.x + av.x; v.y += bv.y + av.y;
                v.z += bv.z + av.z; v.w += bv.w + av.w;
            }
            *(float4*)(C + (size_t)m * ldC + n) = v;
        }
        __syncthreads();
    }
}

// ---------------- fused gate elementwise (step 4), [B, F] layout ----------------
__global__ void k_gate_elem() {
    size_t idx = ((size_t)blockIdx.x * blockDim.x + threadIdx.x) * 4;
    int h = (int)(idx & (HID - 1));
    float4 ci = *(const float4*)&g_c_inp[h];
    float4 cg = *(const float4*)&g_c_ig[h];
    float4 cr = *(const float4*)&g_c_rg[h];
    float4 mv = *(const float4*)&g_mem_v[h];
    float4 pi = *(const float4*)&g_pre[0][idx];
    float4 pg = *(const float4*)&g_pre[1][idx];
    float4 pr = *(const float4*)&g_pre[2][idx];
    float4 o1, o2;
    o1.x = sigf(pi.x + ci.x) * sigf(pg.x + cg.x);
    o1.y = sigf(pi.y + ci.y) * sigf(pg.y + cg.y);
    o1.z = sigf(pi.z + ci.z) * sigf(pg.z + cg.z);
    o1.w = sigf(pi.w + ci.w) * sigf(pg.w + cg.w);
    o2.x = sigf(pr.x + cr.x) * mv.x;
    o2.y = sigf(pr.y + cr.y) * mv.y;
    o2.z = sigf(pr.z + cr.z) * mv.z;
    o2.w = sigf(pr.w + cr.w) * mv.w;
    *(float4*)&g_pre[0][idx] = o1;   // prod -> addm for decoder epilogue
    *(float4*)&g_rgm[idx]    = o2;   // decoder A operand
}

// ---------------- launch ----------------
extern "C" void kernel_launch(void* const* d_in, const int* in_sizes, int n_in,
                              void* d_out, int out_size) {
    P p;
    const float** f = (const float**)&p;
    for (int i = 0; i < 28; i++) f[i] = (const float*)d_in[i];

    float *xT, *pre, *rgm, *hid;
    cudaGetSymbolAddress((void**)&xT,  g_xT);
    cudaGetSymbolAddress((void**)&pre, g_pre);
    cudaGetSymbolAddress((void**)&rgm, g_rgm);
    cudaGetSymbolAddress((void**)&hid, g_hid);
    float* pre0 = pre;
    float* pre1 = pre + (size_t)BATCH * HID;
    float* pre2 = pre + (size_t)2 * BATCH * HID;

    cudaFuncSetAttribute(k_tgemm<0>, cudaFuncAttributeMaxDynamicSharedMemorySize, SMEM_BYTES_G);
    cudaFuncSetAttribute(k_tgemm<1>, cudaFuncAttributeMaxDynamicSharedMemorySize, SMEM_BYTES_G);

    // 1. transpose + vector recurrence + step-4 constants
    k_vec<<<VGRID, VTHREADS>>>(p);

    // 2. stage-1: three fused GEMMs  pre_i[B,1024] = xT @ W_i^T  (768 tiles)
    k_tgemm<0><<<GEMM_GRID, GEMM_THREADS, SMEM_BYTES_G>>>(
        xT, p.W_inp, p.W_ig, p.W_rg, pre0, pre1, pre2,
        IN_DIM, HID, BATCH / TM, HID / TN, 3, nullptr, nullptr);

    // 3. fused sigmoid gates
    k_gate_elem<<<(int)(((size_t)BATCH * HID / 4) / 256), 256>>>();

    // 4. decoder: hid[B,1024] = rgm @ W_dec^T + b_dec + prod  (256 tiles)
    k_tgemm<1><<<GEMM_GRID, GEMM_THREADS, SMEM_BYTES_G>>>(
        rgm, p.W_dec, nullptr, nullptr, hid, nullptr, nullptr,
        MEMD, HID, BATCH / TM, HID / TN, 1, p.b_dec, pre0);

    // 5. out[B,512] = hid @ w_ho^T -> d_out  (128 tiles)
    k_tgemm<0><<<GEMM_GRID, GEMM_THREADS, SMEM_BYTES_G>>>(
        hid, p.w_ho, nullptr, nullptr, (float*)d_out, nullptr, nullptr,
        HID, OUTD, BATCH / TM, OUTD / TN, 1, nullptr, nullptr);
}